// round 8
// baseline (speedup 1.0000x reference)
#include <cuda_runtime.h>

#define EPSF 1e-10f

static const int R  = 32;
static const int NB = 256;          // co-resident blocks (<= 2/SM * 148)
static const int ROWS_PER_BLK = 64; // 2 tiles of 32

__device__ float2   g_scratch[NB * R * R];  // 2 MB partial Grams
__device__ float2   g_red[32 * R * R];      // 256 KB level-1 folds
__device__ float2   g_red2[4 * R * R];      // 32 KB level-2 folds
__device__ float2   g_L[R * R];             // Cholesky factor
__device__ float2   g_W[R * R];             // L^{-H}
// sync counters (never reset): [0..31] gram groups (8 arr each),
// [32..35] fold1 groups (8 arr each), [36] fold2 (4 arr),
// [37] chol (1 arr), [38] W ready (4 arr)
__device__ unsigned g_sync[48];

typedef unsigned long long u64;

// ---- packed f32x2 helpers (FFMA2 only reachable via PTX) ----
__device__ __forceinline__ u64 pk2(float lo, float hi) {
    u64 r; asm("mov.b64 %0, {%1,%2};" : "=l"(r) : "f"(lo), "f"(hi)); return r;
}
__device__ __forceinline__ float2 upk2(u64 v) {
    float lo, hi; asm("mov.b64 {%0,%1}, %2;" : "=f"(lo), "=f"(hi) : "l"(v));
    return make_float2(lo, hi);
}
__device__ __forceinline__ u64 ffma2(u64 a, u64 b, u64 c) {
    u64 d; asm("fma.rn.f32x2 %0, %1, %2, %3;" : "=l"(d) : "l"(a), "l"(b), "l"(c)); return d;
}
__device__ __forceinline__ u64 fadd2(u64 a, u64 b) {
    u64 d; asm("add.rn.f32x2 %0, %1, %2;" : "=l"(d) : "l"(a), "l"(b)); return d;
}

// ---- flag primitives (tid-0 only; caller wraps with __syncthreads) ----
__device__ __forceinline__ unsigned arrive(unsigned* ctr) {
    __threadfence();                       // release
    return atomicAdd(ctr, 1u);
}
__device__ __forceinline__ void spin_ge(unsigned* ctr, unsigned target) {
    while ((int)(*((volatile unsigned*)ctr) - target) < 0) { }
    __threadfence();                       // acquire
}

// ---------------------------------------------------------------------------
// Fused persistent kernel:
//   gram(256) -> [restage overlap] fold1(32) -> fold2(4) -> chol(1)
//   -> backsub(4) -> apply(256, LDS-broadcast FFMA2)
// ---------------------------------------------------------------------------
__global__ void __launch_bounds__(256, 2)
fused_kernel(const float2* __restrict__ x, float2* __restrict__ out) {
    __shared__ __align__(16) char sraw[49152];          // exactly 48 KB
    float4 (*a_dup)[R] = reinterpret_cast<float4(*)[R]>(sraw);           // 16KB
    float4 (*b_ns)[R]  = reinterpret_cast<float4(*)[R]>(sraw + 16384);   // 16KB
    u64*    red        = reinterpret_cast<u64*>(sraw + 32768);           // 16KB
    float2* As         = reinterpret_cast<float2*>(sraw + 32768);        // overlay
    float2* colbuf     = reinterpret_cast<float2*>(sraw + 32768 + 8448); // overlay

    const int tid  = threadIdx.x;
    const int b    = blockIdx.x;
    const int lane = tid & 31;
    const int wid  = tid >> 5;

    const int sr = tid >> 3;           // staging row 0..31
    const int sc = (tid & 7) * 4;      // staging col base (complex)
    const float2* xb = x + (size_t)b * (ROWS_PER_BLK * R);

    // ======================= Phase 1: partial Gram =======================
    {
        const int mg  = tid >> 6;
        const int t64 = tid & 63;
        const int i0  = (t64 >> 3) * 4;
        const int j0  = (t64 & 7) * 4;

        u64 acc[4][4];
        #pragma unroll
        for (int a_ = 0; a_ < 4; ++a_)
            #pragma unroll
            for (int c_ = 0; c_ < 4; ++c_) acc[a_][c_] = 0ull;

        for (int t = 0; t < 2; ++t) {
            float4 p0 = *(const float4*)(xb + (t * 32 + sr) * R + sc);
            float4 p1 = *(const float4*)(xb + (t * 32 + sr) * R + sc + 2);

            a_dup[sr][sc + 0] = make_float4(p0.x, p0.x, p0.y, p0.y);
            b_ns [sr][sc + 0] = make_float4(p0.x, p0.y, p0.y, -p0.x);
            a_dup[sr][sc + 1] = make_float4(p0.z, p0.z, p0.w, p0.w);
            b_ns [sr][sc + 1] = make_float4(p0.z, p0.w, p0.w, -p0.z);
            a_dup[sr][sc + 2] = make_float4(p1.x, p1.x, p1.y, p1.y);
            b_ns [sr][sc + 2] = make_float4(p1.x, p1.y, p1.y, -p1.x);
            a_dup[sr][sc + 3] = make_float4(p1.z, p1.z, p1.w, p1.w);
            b_ns [sr][sc + 3] = make_float4(p1.z, p1.w, p1.w, -p1.z);
            __syncthreads();

            #pragma unroll
            for (int mm = 0; mm < 8; ++mm) {
                const int m = mg + mm * 4;
                u64 A[4][2], B[4][2];
                #pragma unroll
                for (int d = 0; d < 4; ++d) {
                    float4 av = a_dup[m][i0 + d];
                    A[d][0] = pk2(av.x, av.y); A[d][1] = pk2(av.z, av.w);
                    float4 bv = b_ns[m][j0 + d];
                    B[d][0] = pk2(bv.x, bv.y); B[d][1] = pk2(bv.z, bv.w);
                }
                #pragma unroll
                for (int di = 0; di < 4; ++di)
                    #pragma unroll
                    for (int dj = 0; dj < 4; ++dj) {
                        acc[di][dj] = ffma2(A[di][0], B[dj][0], acc[di][dj]);
                        acc[di][dj] = ffma2(A[di][1], B[dj][1], acc[di][dj]);
                    }
            }
            __syncthreads();
        }

        // cross-m-group tree reduce in 16KB red region: (1->0),(3->2),(2->0)
        if (mg == 1 || mg == 3) {
            u64* dst = red + ((mg >> 1) * 64 + t64) * 16;
            #pragma unroll
            for (int di = 0; di < 4; ++di)
                #pragma unroll
                for (int dj = 0; dj < 4; ++dj) dst[di * 4 + dj] = acc[di][dj];
        }
        __syncthreads();
        if (mg == 0 || mg == 2) {
            const u64* srcp = red + ((mg >> 1) * 64 + t64) * 16;
            #pragma unroll
            for (int di = 0; di < 4; ++di)
                #pragma unroll
                for (int dj = 0; dj < 4; ++dj)
                    acc[di][dj] = fadd2(acc[di][dj], srcp[di * 4 + dj]);
        }
        __syncthreads();
        if (mg == 2) {
            u64* dst = red + t64 * 16;
            #pragma unroll
            for (int di = 0; di < 4; ++di)
                #pragma unroll
                for (int dj = 0; dj < 4; ++dj) dst[di * 4 + dj] = acc[di][dj];
        }
        __syncthreads();
        if (mg == 0) {
            const u64* srcp = red + t64 * 16;
            #pragma unroll
            for (int di = 0; di < 4; ++di)
                #pragma unroll
                for (int dj = 0; dj < 4; ++dj)
                    acc[di][dj] = fadd2(acc[di][dj], srcp[di * 4 + dj]);
            float4* gout = reinterpret_cast<float4*>(g_scratch + b * (R * R));
            #pragma unroll
            for (int di = 0; di < 4; ++di) {
                float2 c0 = upk2(acc[di][0]), c1 = upk2(acc[di][1]);
                float2 c2 = upk2(acc[di][2]), c3 = upk2(acc[di][3]);
                int base = ((i0 + di) * R + j0) >> 1;
                gout[base]     = make_float4(c0.x, c0.y, c1.x, c1.y);
                gout[base + 1] = make_float4(c2.x, c2.y, c3.x, c3.y);
            }
        }
    }
    __syncthreads();

    // epoch ticket from own gram-group arrival (8 arrivals/group/replay)
    unsigned e = 0;
    if (tid == 0) e = arrive(&g_sync[b >> 3]) >> 3;

    // ===== Restage rows 0..31 into b_ns as (r,r,i,i) — overlaps middle ====
    // (a_dup already holds rows 32..63 in this format from gram tile t=1)
    {
        float4 p0 = *(const float4*)(xb + sr * R + sc);
        float4 p1 = *(const float4*)(xb + sr * R + sc + 2);
        b_ns[sr][sc + 0] = make_float4(p0.x, p0.x, p0.y, p0.y);
        b_ns[sr][sc + 1] = make_float4(p0.z, p0.z, p0.w, p0.w);
        b_ns[sr][sc + 2] = make_float4(p1.x, p1.x, p1.y, p1.y);
        b_ns[sr][sc + 3] = make_float4(p1.z, p1.z, p1.w, p1.w);
    }

    // ============ Phase 2a: blocks 0..31 fold 8 scratch tiles ============
    if (b < 32) {
        if (tid == 0) spin_ge(&g_sync[b], (e + 1) * 8);
        __syncthreads();
        const float4* src = (const float4*)g_scratch + (size_t)b * 8 * 512;
        float4* dst = (float4*)g_red + (size_t)b * 512;
        #pragma unroll
        for (int h = 0; h < 2; ++h) {
            int i4 = tid + h * 256;
            float4 s = __ldcg(src + i4);
            #pragma unroll
            for (int i = 1; i < 8; ++i) {
                float4 a = __ldcg(src + (size_t)i * 512 + i4);
                s.x += a.x; s.y += a.y; s.z += a.z; s.w += a.w;
            }
            dst[i4] = s;
        }
        __syncthreads();
        if (tid == 0) arrive(&g_sync[32 + (b >> 3)]);
    }

    // ============ Phase 2b: blocks 0..3 fold 8 red tiles =================
    if (b < 4) {
        if (tid == 0) spin_ge(&g_sync[32 + b], (e + 1) * 8);
        __syncthreads();
        const float4* src = (const float4*)g_red + (size_t)b * 8 * 512;
        float4* dst = (float4*)g_red2 + (size_t)b * 512;
        #pragma unroll
        for (int h = 0; h < 2; ++h) {
            int i4 = tid + h * 256;
            float4 s = __ldcg(src + i4);
            #pragma unroll
            for (int i = 1; i < 8; ++i) {
                float4 a = __ldcg(src + (size_t)i * 512 + i4);
                s.x += a.x; s.y += a.y; s.z += a.z; s.w += a.w;
            }
            dst[i4] = s;
        }
        __syncthreads();
        if (tid == 0) arrive(&g_sync[36]);
    }

    // ====== Phase 2c+3: block 0 — fold 4 -> G, register Cholesky -> L ====
    if (b == 0) {
        if (tid == 0) spin_ge(&g_sync[36], (e + 1) * 4);
        __syncthreads();
        const float4* src = (const float4*)g_red2;
        #pragma unroll
        for (int h = 0; h < 2; ++h) {
            int f4 = tid + h * 256;
            float4 s = __ldcg(src + f4);
            #pragma unroll
            for (int i = 1; i < 4; ++i) {
                float4 a = __ldcg(src + (size_t)i * 512 + f4);
                s.x += a.x; s.y += a.y; s.z += a.z; s.w += a.w;
            }
            int c = f4 * 2;
            As[(c >> 5) * 33 + (c & 31)]             = make_float2(s.x, s.y);
            As[((c + 1) >> 5) * 33 + ((c + 1) & 31)] = make_float2(s.z, s.w);
        }
        __syncthreads();

        // register (p,q)-parallel Cholesky: thread holds A[wid+8s][lane]
        float2 a4[4];
        #pragma unroll
        for (int s = 0; s < 4; ++s) a4[s] = As[(wid + 8 * s) * 33 + lane];

        for (int k = 0; k < R; ++k) {
            float2* cb = colbuf + (k & 1) * 32;
            if (lane == k) {
                #pragma unroll
                for (int s = 0; s < 4; ++s) cb[wid + 8 * s] = a4[s];
            }
            __syncthreads();
            float dkk = cb[k].x;
            float rd  = rsqrtf(dkk + EPSF);
            float2 cq = cb[lane];
            float2 lq = make_float2(cq.x * rd, cq.y * rd);
            #pragma unroll
            for (int s = 0; s < 4; ++s) {
                int p = wid + 8 * s;
                float2 cp = cb[p];
                float2 lp = make_float2(cp.x * rd, cp.y * rd);
                if (p > k && lane > k) {
                    a4[s].x -= lp.x * lq.x + lp.y * lq.y;
                    a4[s].y -= lp.y * lq.x - lp.x * lq.y;
                }
                if (lane == k) {
                    if (p == k)      a4[s] = make_float2((dkk + EPSF) * rd, 0.f);
                    else if (p > k)  a4[s] = lp;
                }
            }
        }
        #pragma unroll
        for (int s = 0; s < 4; ++s) g_L[(wid + 8 * s) * R + lane] = a4[s];
        __syncthreads();
        if (tid == 0) arrive(&g_sync[37]);
    }

    // ========= Phase 3b: blocks 0-3 backsub, one warp per column =========
    if (b < 4) {
        if (tid == 0) spin_ge(&g_sync[37], e + 1);
        __syncthreads();
        for (int el = tid; el < R * R; el += 256)
            As[(el >> 5) * 33 + (el & 31)] = __ldcg(&g_L[el]);
        __syncthreads();

        const int j = b * 8 + wid;
        const float invd = 1.0f / As[lane * 33 + lane].x;
        float2 accw = make_float2(0.f, 0.f);
        float2 wp   = make_float2(0.f, 0.f);
        for (int qq = j; qq >= 0; --qq) {
            float cre = (((lane == j) ? 1.f : 0.f) - accw.x) * invd;
            float cim = (-accw.y) * invd;
            float wr = __shfl_sync(0xffffffffu, cre, qq);
            float wi = __shfl_sync(0xffffffffu, cim, qq);
            if (lane == qq) { wp.x = wr; wp.y = wi; }
            float2 lqp = As[qq * 33 + lane];
            if (lane < qq) {
                accw.x += lqp.x * wr + lqp.y * wi;
                accw.y += lqp.x * wi - lqp.y * wr;
            }
        }
        g_W[lane * R + j] = wp;   // W[k][j]
        __syncthreads();
        if (tid == 0) arrive(&g_sync[38]);
    }

    // ============ Phase 4: apply, LDS-broadcast + FFMA2 ==================
    if (tid == 0) spin_ge(&g_sync[38], (e + 1) * 4);
    __syncthreads();   // covers restage visibility AND W readiness
    {
        // lane j's W column, packed (wr,wi)
        u64 wpk[R];
        #pragma unroll
        for (int k = 0; k < R; ++k) {
            float2 wv = __ldcg(&g_W[k * R + lane]);
            wpk[k] = pk2(wv.x, wv.y);
        }

        // warps 0-3: rows 0-31 (b_ns), warps 4-7: rows 32-63 (a_dup)
        const float4 (*xt)[R] = (wid < 4)
            ? (const float4(*)[R])b_ns : (const float4(*)[R])a_dup;
        const int r0    = (wid & 3) * 8;
        const int mbase = (wid < 4) ? 0 : 32;
        float2* ob = out + (size_t)b * (ROWS_PER_BLK * R);

        #pragma unroll
        for (int r = 0; r < 8; r += 2) {
            const int m0 = r0 + r, m1 = m0 + 1;
            u64 aa0 = 0ull, ab0 = 0ull, aa1 = 0ull, ab1 = 0ull;
            #pragma unroll
            for (int k = 0; k < R; ++k) {
                ulonglong2 v0 = *(const ulonglong2*)&xt[m0][k]; // ((ar,ar),(ai,ai))
                ulonglong2 v1 = *(const ulonglong2*)&xt[m1][k];
                aa0 = ffma2(v0.x, wpk[k], aa0);
                ab0 = ffma2(v0.y, wpk[k], ab0);
                aa1 = ffma2(v1.x, wpk[k], aa1);
                ab1 = ffma2(v1.y, wpk[k], ab1);
            }
            float2 A0 = upk2(aa0), B0 = upk2(ab0);
            float2 A1 = upk2(aa1), B1 = upk2(ab1);
            ob[(mbase + m0) * R + lane] = make_float2(A0.x - B0.y, A0.y + B0.x);
            ob[(mbase + m1) * R + lane] = make_float2(A1.x - B1.y, A1.y + B1.x);
        }
    }
}

// ---------------------------------------------------------------------------
extern "C" void kernel_launch(void* const* d_in, const int* in_sizes, int n_in,
                              void* d_out, int out_size) {
    const float2* x  = (const float2*)d_in[0];
    float2* out      = (float2*)d_out;

    fused_kernel<<<NB, 256>>>(x, out);
}

// round 9
// speedup vs baseline: 1.2500x; 1.2500x over previous
#include <cuda_runtime.h>

#define EPSF 1e-10f

static const int R  = 32;
static const int NB = 256;          // co-resident blocks (<= 2/SM * 148)
static const int ROWS_PER_BLK = 64; // 2 tiles of 32

__device__ float2   g_scratch[NB * R * R];  // 2 MB partial Grams
__device__ float2   g_red[32 * R * R];      // 256 KB level-1 folds
__device__ float2   g_red2[4 * R * R];      // 32 KB level-2 folds
__device__ float2   g_L[R * R];             // Cholesky factor
__device__ float2   g_W[R * R];             // L^{-H}
// sync counters (never reset): [0..31] gram groups (8 arr each),
// [32..35] fold1 groups (8 arr each), [36] fold2 (4 arr),
// [37] chol (1 arr), [38] W ready (4 arr)
__device__ unsigned g_sync[48];

typedef unsigned long long u64;

// ---- packed f32x2 helpers (FFMA2 only reachable via PTX) ----
__device__ __forceinline__ u64 pk2(float lo, float hi) {
    u64 r; asm("mov.b64 %0, {%1,%2};" : "=l"(r) : "f"(lo), "f"(hi)); return r;
}
__device__ __forceinline__ float2 upk2(u64 v) {
    float lo, hi; asm("mov.b64 {%0,%1}, %2;" : "=f"(lo), "=f"(hi) : "l"(v));
    return make_float2(lo, hi);
}
__device__ __forceinline__ u64 ffma2(u64 a, u64 b, u64 c) {
    u64 d; asm("fma.rn.f32x2 %0, %1, %2, %3;" : "=l"(d) : "l"(a), "l"(b), "l"(c)); return d;
}
__device__ __forceinline__ u64 fadd2(u64 a, u64 b) {
    u64 d; asm("add.rn.f32x2 %0, %1, %2;" : "=l"(d) : "l"(a), "l"(b)); return d;
}

// ---- flag primitives (tid-0 only; caller wraps with __syncthreads) ----
__device__ __forceinline__ unsigned arrive(unsigned* ctr) {
    __threadfence();                       // release
    return atomicAdd(ctr, 1u);
}
__device__ __forceinline__ void spin_ge(unsigned* ctr, unsigned target) {
    while ((int)(*((volatile unsigned*)ctr) - target) < 0) { }
    __threadfence();                       // acquire
}

// Bank-conflict-free smem column map: logical col c = 4a+d  ->  slot 8d+a.
// B-reads (fixed d, a=0..7) land on 8 distinct bank quads -> 1 phase.
#define SWZ(a, d) (8 * (d) + (a))

// ---------------------------------------------------------------------------
// Fused persistent kernel, producer-consumer synchronized:
//   gram(256) -> fold1(32) -> fold2(4) -> chol(1) -> backsub(4) -> apply(256)
// ---------------------------------------------------------------------------
__global__ void __launch_bounds__(256, 2)
fused_kernel(const float2* __restrict__ x, float2* __restrict__ out) {
    __shared__ __align__(16) char sraw[32 * 1024 + 512];
    float4 (*a_dup)[R] = reinterpret_cast<float4(*)[R]>(sraw);          // 16KB
    float4 (*b_ns)[R]  = reinterpret_cast<float4(*)[R]>(sraw + 16384);  // 16KB
    u64*    red        = reinterpret_cast<u64*>(sraw);                  // reused
    float2* As         = reinterpret_cast<float2*>(sraw);               // reused
    float2* colbuf     = reinterpret_cast<float2*>(sraw + 28 * 1024);   // [2][32]

    const int tid  = threadIdx.x;
    const int b    = blockIdx.x;
    const int lane = tid & 31;
    const int wid  = tid >> 5;

    // ======================= Phase 1: partial Gram =======================
    {
        const int mg  = tid >> 6;
        const int t64 = tid & 63;
        const int ia  = t64 >> 3;          // A column group (i0 = 4*ia)
        const int ja  = t64 & 7;           // B column group (j0 = 4*ja)
        const int i0  = ia * 4;
        const int j0  = ja * 4;
        const int sr  = tid >> 3;          // staging row 0..31
        const int sa  = tid & 7;           // staging col group a

        const float2* xb = x + (size_t)b * (ROWS_PER_BLK * R);

        u64 acc[4][4];
        #pragma unroll
        for (int a_ = 0; a_ < 4; ++a_)
            #pragma unroll
            for (int c_ = 0; c_ < 4; ++c_) acc[a_][c_] = 0ull;

        for (int t = 0; t < 2; ++t) {
            // this thread stages logical cols 4*sa .. 4*sa+3 of row sr
            float4 p0 = *(const float4*)(xb + (t * 32 + sr) * R + sa * 4);
            float4 p1 = *(const float4*)(xb + (t * 32 + sr) * R + sa * 4 + 2);

            a_dup[sr][SWZ(sa, 0)] = make_float4(p0.x, p0.x, p0.y, p0.y);
            b_ns [sr][SWZ(sa, 0)] = make_float4(p0.x, p0.y, p0.y, -p0.x);
            a_dup[sr][SWZ(sa, 1)] = make_float4(p0.z, p0.z, p0.w, p0.w);
            b_ns [sr][SWZ(sa, 1)] = make_float4(p0.z, p0.w, p0.w, -p0.z);
            a_dup[sr][SWZ(sa, 2)] = make_float4(p1.x, p1.x, p1.y, p1.y);
            b_ns [sr][SWZ(sa, 2)] = make_float4(p1.x, p1.y, p1.y, -p1.x);
            a_dup[sr][SWZ(sa, 3)] = make_float4(p1.z, p1.z, p1.w, p1.w);
            b_ns [sr][SWZ(sa, 3)] = make_float4(p1.z, p1.w, p1.w, -p1.z);
            __syncthreads();

            #pragma unroll
            for (int mm = 0; mm < 8; ++mm) {
                const int m = mg + mm * 4;
                u64 A[4][2], B[4][2];
                #pragma unroll
                for (int d = 0; d < 4; ++d) {
                    float4 av = a_dup[m][SWZ(ia, d)];   // logical col i0+d
                    A[d][0] = pk2(av.x, av.y); A[d][1] = pk2(av.z, av.w);
                    float4 bv = b_ns[m][SWZ(ja, d)];    // logical col j0+d
                    B[d][0] = pk2(bv.x, bv.y); B[d][1] = pk2(bv.z, bv.w);
                }
                #pragma unroll
                for (int di = 0; di < 4; ++di)
                    #pragma unroll
                    for (int dj = 0; dj < 4; ++dj) {
                        acc[di][dj] = ffma2(A[di][0], B[dj][0], acc[di][dj]);
                        acc[di][dj] = ffma2(A[di][1], B[dj][1], acc[di][dj]);
                    }
            }
            __syncthreads();
        }

        if (mg > 0) {
            u64* dst = red + ((mg - 1) * 64 + t64) * 16;
            #pragma unroll
            for (int di = 0; di < 4; ++di)
                #pragma unroll
                for (int dj = 0; dj < 4; ++dj) dst[di * 4 + dj] = acc[di][dj];
        }
        __syncthreads();
        if (mg == 0) {
            #pragma unroll
            for (int g = 0; g < 3; ++g) {
                const u64* srcp = red + (g * 64 + t64) * 16;
                #pragma unroll
                for (int di = 0; di < 4; ++di)
                    #pragma unroll
                    for (int dj = 0; dj < 4; ++dj)
                        acc[di][dj] = fadd2(acc[di][dj], srcp[di * 4 + dj]);
            }
            float4* gout = reinterpret_cast<float4*>(g_scratch + b * (R * R));
            #pragma unroll
            for (int di = 0; di < 4; ++di) {
                float2 c0 = upk2(acc[di][0]), c1 = upk2(acc[di][1]);
                float2 c2 = upk2(acc[di][2]), c3 = upk2(acc[di][3]);
                int base = ((i0 + di) * R + j0) >> 1;
                gout[base]     = make_float4(c0.x, c0.y, c1.x, c1.y);
                gout[base + 1] = make_float4(c2.x, c2.y, c3.x, c3.y);
            }
        }
    }
    __syncthreads();

    // epoch ticket from own gram-group arrival (8 arrivals/group/replay)
    unsigned e = 0;
    if (tid == 0) e = arrive(&g_sync[b >> 3]) >> 3;

    // ============ Phase 2a: blocks 0..31 fold 8 scratch tiles ============
    if (b < 32) {
        if (tid == 0) spin_ge(&g_sync[b], (e + 1) * 8);
        __syncthreads();
        const float4* src = (const float4*)g_scratch + (size_t)b * 8 * 512;
        float4* dst = (float4*)g_red + (size_t)b * 512;
        #pragma unroll
        for (int h = 0; h < 2; ++h) {
            int i4 = tid + h * 256;
            float4 s = __ldcg(src + i4);
            #pragma unroll
            for (int i = 1; i < 8; ++i) {
                float4 a = __ldcg(src + (size_t)i * 512 + i4);
                s.x += a.x; s.y += a.y; s.z += a.z; s.w += a.w;
            }
            dst[i4] = s;
        }
        __syncthreads();
        if (tid == 0) arrive(&g_sync[32 + (b >> 3)]);
    }

    // ============ Phase 2b: blocks 0..3 fold 8 red tiles =================
    if (b < 4) {
        if (tid == 0) spin_ge(&g_sync[32 + b], (e + 1) * 8);
        __syncthreads();
        const float4* src = (const float4*)g_red + (size_t)b * 8 * 512;
        float4* dst = (float4*)g_red2 + (size_t)b * 512;
        #pragma unroll
        for (int h = 0; h < 2; ++h) {
            int i4 = tid + h * 256;
            float4 s = __ldcg(src + i4);
            #pragma unroll
            for (int i = 1; i < 8; ++i) {
                float4 a = __ldcg(src + (size_t)i * 512 + i4);
                s.x += a.x; s.y += a.y; s.z += a.z; s.w += a.w;
            }
            dst[i4] = s;
        }
        __syncthreads();
        if (tid == 0) arrive(&g_sync[36]);
    }

    // ====== Phase 2c+3: block 0 — fold 4 -> G, register Cholesky -> L ====
    if (b == 0) {
        if (tid == 0) spin_ge(&g_sync[36], (e + 1) * 4);
        __syncthreads();
        const float4* src = (const float4*)g_red2;
        #pragma unroll
        for (int h = 0; h < 2; ++h) {
            int f4 = tid + h * 256;
            float4 s = __ldcg(src + f4);
            #pragma unroll
            for (int i = 1; i < 4; ++i) {
                float4 a = __ldcg(src + (size_t)i * 512 + f4);
                s.x += a.x; s.y += a.y; s.z += a.z; s.w += a.w;
            }
            int c = f4 * 2;
            As[(c >> 5) * 33 + (c & 31)]             = make_float2(s.x, s.y);
            As[((c + 1) >> 5) * 33 + ((c + 1) & 31)] = make_float2(s.z, s.w);
        }
        __syncthreads();

        // register (p,q)-parallel Cholesky: thread holds A[wid+8s][lane]
        float2 a4[4];
        #pragma unroll
        for (int s = 0; s < 4; ++s) a4[s] = As[(wid + 8 * s) * 33 + lane];

        for (int k = 0; k < R; ++k) {
            float2* cb = colbuf + (k & 1) * 32;
            if (lane == k) {
                #pragma unroll
                for (int s = 0; s < 4; ++s) cb[wid + 8 * s] = a4[s];
            }
            __syncthreads();
            float dkk = cb[k].x;
            float rd  = rsqrtf(dkk + EPSF);
            float2 cq = cb[lane];
            float2 lq = make_float2(cq.x * rd, cq.y * rd);
            #pragma unroll
            for (int s = 0; s < 4; ++s) {
                int p = wid + 8 * s;
                float2 cp = cb[p];
                float2 lp = make_float2(cp.x * rd, cp.y * rd);
                if (p > k && lane > k) {
                    a4[s].x -= lp.x * lq.x + lp.y * lq.y;
                    a4[s].y -= lp.y * lq.x - lp.x * lq.y;
                }
                if (lane == k) {
                    if (p == k)      a4[s] = make_float2((dkk + EPSF) * rd, 0.f);
                    else if (p > k)  a4[s] = lp;
                }
            }
        }
        #pragma unroll
        for (int s = 0; s < 4; ++s) g_L[(wid + 8 * s) * R + lane] = a4[s];
        __syncthreads();
        if (tid == 0) arrive(&g_sync[37]);
    }

    // ========= Phase 3b: blocks 0-3 backsub, one warp per column =========
    if (b < 4) {
        if (tid == 0) spin_ge(&g_sync[37], e + 1);
        __syncthreads();
        for (int el = tid; el < R * R; el += 256)
            As[(el >> 5) * 33 + (el & 31)] = __ldcg(&g_L[el]);
        __syncthreads();

        const int j = b * 8 + wid;
        const float invd = 1.0f / As[lane * 33 + lane].x;
        float2 accw = make_float2(0.f, 0.f);
        float2 wp   = make_float2(0.f, 0.f);
        for (int qq = j; qq >= 0; --qq) {
            float cre = (((lane == j) ? 1.f : 0.f) - accw.x) * invd;
            float cim = (-accw.y) * invd;
            float wr = __shfl_sync(0xffffffffu, cre, qq);
            float wi = __shfl_sync(0xffffffffu, cim, qq);
            if (lane == qq) { wp.x = wr; wp.y = wi; }
            float2 lqp = As[qq * 33 + lane];
            if (lane < qq) {
                accw.x += lqp.x * wr + lqp.y * wi;
                accw.y += lqp.x * wi - lqp.y * wr;
            }
        }
        g_W[lane * R + j] = wp;   // W[k][j]
        __syncthreads();
        if (tid == 0) arrive(&g_sync[38]);
    }

    // ================= Phase 4: apply  Q = X * W =========================
    if (tid == 0) spin_ge(&g_sync[38], (e + 1) * 4);
    __syncthreads();
    {
        float wr[R], wi[R];
        #pragma unroll
        for (int k = 0; k < R; ++k) {
            float2 wv = __ldcg(&g_W[k * R + lane]);
            wr[k] = wv.x; wi[k] = wv.y;
        }

        const int gw = b * 8 + wid;
        const int m0 = gw * 8;
        #pragma unroll
        for (int r = 0; r < 8; ++r) {
            int m = m0 + r;
            float2 v = x[m * R + lane];
            float or_ = 0.f, oi_ = 0.f;
            #pragma unroll
            for (int k = 0; k < R; ++k) {
                float ar = __shfl_sync(0xffffffffu, v.x, k);
                float ai = __shfl_sync(0xffffffffu, v.y, k);
                or_ += ar * wr[k] - ai * wi[k];
                oi_ += ar * wi[k] + ai * wr[k];
            }
            out[m * R + lane] = make_float2(or_, oi_);
        }
    }
}

// ---------------------------------------------------------------------------
extern "C" void kernel_launch(void* const* d_in, const int* in_sizes, int n_in,
                              void* d_out, int out_size) {
    const float2* x  = (const float2*)d_in[0];
    float2* out      = (float2*)d_out;

    fused_kernel<<<NB, 256>>>(x, out);
}

// round 10
// speedup vs baseline: 1.2998x; 1.0399x over previous
#include <cuda_runtime.h>

#define EPSF 1e-10f

static const int R  = 32;
static const int NB = 256;          // co-resident blocks (<= 2/SM * 148)
static const int ROWS_PER_BLK = 64; // 2 tiles of 32

__device__ float2   g_scratch[NB * R * R];  // 2 MB partial Grams
__device__ float2   g_red[32 * R * R];      // 256 KB level-1 folds
__device__ float2   g_red2[4 * R * R];      // 32 KB level-2 folds
__device__ float2   g_L[R * R];             // Cholesky factor
__device__ float2   g_W[R * R];             // L^{-H}
// sync counters (never reset): [0..31] gram groups (8 arr each),
// [32..35] fold1 groups (8 arr each), [36] fold2 (4 arr),
// [37] chol (1 arr), [38] W ready (4 arr)
__device__ unsigned g_sync[48];

typedef unsigned long long u64;

// ---- packed f32x2 helpers (FFMA2 only reachable via PTX) ----
__device__ __forceinline__ u64 pk2(float lo, float hi) {
    u64 r; asm("mov.b64 %0, {%1,%2};" : "=l"(r) : "f"(lo), "f"(hi)); return r;
}
__device__ __forceinline__ float2 upk2(u64 v) {
    float lo, hi; asm("mov.b64 {%0,%1}, %2;" : "=f"(lo), "=f"(hi) : "l"(v));
    return make_float2(lo, hi);
}
__device__ __forceinline__ u64 ffma2(u64 a, u64 b, u64 c) {
    u64 d; asm("fma.rn.f32x2 %0, %1, %2, %3;" : "=l"(d) : "l"(a), "l"(b), "l"(c)); return d;
}
__device__ __forceinline__ u64 fadd2(u64 a, u64 b) {
    u64 d; asm("add.rn.f32x2 %0, %1, %2;" : "=l"(d) : "l"(a), "l"(b)); return d;
}

// ---- flag primitives (tid-0 only; caller wraps with __syncthreads) ----
__device__ __forceinline__ unsigned arrive(unsigned* ctr) {
    __threadfence();                       // release
    return atomicAdd(ctr, 1u);
}
__device__ __forceinline__ void spin_ge(unsigned* ctr, unsigned target) {
    while ((int)(*((volatile unsigned*)ctr) - target) < 0) { }
    __threadfence();                       // acquire
}

// Bank-conflict-free smem column map: logical col c = 4a+d  ->  slot 8d+a.
#define SWZ(a, d) (8 * (d) + (a))

// ---------------------------------------------------------------------------
// Fused persistent kernel, producer-consumer synchronized:
//   gram(256) -> [restage overlap] fold1(32) -> fold2(4) -> chol(1)
//   -> backsub(4) -> apply(256, broadcast-LDS + FFMA2)
// ---------------------------------------------------------------------------
__global__ void __launch_bounds__(256, 2)
fused_kernel(const float2* __restrict__ x, float2* __restrict__ out) {
    __shared__ __align__(16) char sraw[32 * 1024 + 512];
    float4 (*a_dup)[R] = reinterpret_cast<float4(*)[R]>(sraw);          // 16KB
    float4 (*b_ns)[R]  = reinterpret_cast<float4(*)[R]>(sraw + 16384);  // 16KB
    u64*    red        = reinterpret_cast<u64*>(sraw);                  // reused
    float2* As         = reinterpret_cast<float2*>(sraw);               // reused
    float2* colbuf     = reinterpret_cast<float2*>(sraw + 28 * 1024);   // [2][32]

    const int tid  = threadIdx.x;
    const int b    = blockIdx.x;
    const int lane = tid & 31;
    const int wid  = tid >> 5;

    const float2* xblk = x + (size_t)b * (ROWS_PER_BLK * R);

    // ======================= Phase 1: partial Gram =======================
    {
        const int mg  = tid >> 6;
        const int t64 = tid & 63;
        const int ia  = t64 >> 3;          // A column group (i0 = 4*ia)
        const int ja  = t64 & 7;           // B column group (j0 = 4*ja)
        const int i0  = ia * 4;
        const int j0  = ja * 4;
        const int sr  = tid >> 3;          // staging row 0..31
        const int sa  = tid & 7;           // staging col group a

        u64 acc[4][4];
        #pragma unroll
        for (int a_ = 0; a_ < 4; ++a_)
            #pragma unroll
            for (int c_ = 0; c_ < 4; ++c_) acc[a_][c_] = 0ull;

        for (int t = 0; t < 2; ++t) {
            float4 p0 = *(const float4*)(xblk + (t * 32 + sr) * R + sa * 4);
            float4 p1 = *(const float4*)(xblk + (t * 32 + sr) * R + sa * 4 + 2);

            a_dup[sr][SWZ(sa, 0)] = make_float4(p0.x, p0.x, p0.y, p0.y);
            b_ns [sr][SWZ(sa, 0)] = make_float4(p0.x, p0.y, p0.y, -p0.x);
            a_dup[sr][SWZ(sa, 1)] = make_float4(p0.z, p0.z, p0.w, p0.w);
            b_ns [sr][SWZ(sa, 1)] = make_float4(p0.z, p0.w, p0.w, -p0.z);
            a_dup[sr][SWZ(sa, 2)] = make_float4(p1.x, p1.x, p1.y, p1.y);
            b_ns [sr][SWZ(sa, 2)] = make_float4(p1.x, p1.y, p1.y, -p1.x);
            a_dup[sr][SWZ(sa, 3)] = make_float4(p1.z, p1.z, p1.w, p1.w);
            b_ns [sr][SWZ(sa, 3)] = make_float4(p1.z, p1.w, p1.w, -p1.z);
            __syncthreads();

            #pragma unroll
            for (int mm = 0; mm < 8; ++mm) {
                const int m = mg + mm * 4;
                u64 A[4][2], B[4][2];
                #pragma unroll
                for (int d = 0; d < 4; ++d) {
                    float4 av = a_dup[m][SWZ(ia, d)];
                    A[d][0] = pk2(av.x, av.y); A[d][1] = pk2(av.z, av.w);
                    float4 bv = b_ns[m][SWZ(ja, d)];
                    B[d][0] = pk2(bv.x, bv.y); B[d][1] = pk2(bv.z, bv.w);
                }
                #pragma unroll
                for (int di = 0; di < 4; ++di)
                    #pragma unroll
                    for (int dj = 0; dj < 4; ++dj) {
                        acc[di][dj] = ffma2(A[di][0], B[dj][0], acc[di][dj]);
                        acc[di][dj] = ffma2(A[di][1], B[dj][1], acc[di][dj]);
                    }
            }
            __syncthreads();
        }

        if (mg > 0) {
            u64* dst = red + ((mg - 1) * 64 + t64) * 16;
            #pragma unroll
            for (int di = 0; di < 4; ++di)
                #pragma unroll
                for (int dj = 0; dj < 4; ++dj) dst[di * 4 + dj] = acc[di][dj];
        }
        __syncthreads();
        if (mg == 0) {
            #pragma unroll
            for (int g = 0; g < 3; ++g) {
                const u64* srcp = red + (g * 64 + t64) * 16;
                #pragma unroll
                for (int di = 0; di < 4; ++di)
                    #pragma unroll
                    for (int dj = 0; dj < 4; ++dj)
                        acc[di][dj] = fadd2(acc[di][dj], srcp[di * 4 + dj]);
            }
            float4* gout = reinterpret_cast<float4*>(g_scratch + b * (R * R));
            #pragma unroll
            for (int di = 0; di < 4; ++di) {
                float2 c0 = upk2(acc[di][0]), c1 = upk2(acc[di][1]);
                float2 c2 = upk2(acc[di][2]), c3 = upk2(acc[di][3]);
                int base = ((i0 + di) * R + j0) >> 1;
                gout[base]     = make_float4(c0.x, c0.y, c1.x, c1.y);
                gout[base + 1] = make_float4(c2.x, c2.y, c3.x, c3.y);
            }
        }
    }
    __syncthreads();

    // epoch ticket from own gram-group arrival (8 arrivals/group/replay)
    unsigned e = 0;
    if (tid == 0) e = arrive(&g_sync[b >> 3]) >> 3;

    // ===== Restage x into (r,r,i,i) SWZ layout for the LDS apply =========
    // rows 0..31 -> b_ns, rows 32..63 -> a_dup. Blocks >=4 do it here so it
    // overlaps the fold/chol/backsub chain; blocks 0-3 defer (their smem is
    // clobbered by As/colbuf during chol+backsub).
    if (b >= 4) {
        const int sr = tid >> 3, sa = tid & 7;
        float4 p0 = *(const float4*)(xblk + sr * R + sa * 4);
        float4 p1 = *(const float4*)(xblk + sr * R + sa * 4 + 2);
        float4 q0 = *(const float4*)(xblk + (32 + sr) * R + sa * 4);
        float4 q1 = *(const float4*)(xblk + (32 + sr) * R + sa * 4 + 2);
        b_ns [sr][SWZ(sa, 0)] = make_float4(p0.x, p0.x, p0.y, p0.y);
        b_ns [sr][SWZ(sa, 1)] = make_float4(p0.z, p0.z, p0.w, p0.w);
        b_ns [sr][SWZ(sa, 2)] = make_float4(p1.x, p1.x, p1.y, p1.y);
        b_ns [sr][SWZ(sa, 3)] = make_float4(p1.z, p1.z, p1.w, p1.w);
        a_dup[sr][SWZ(sa, 0)] = make_float4(q0.x, q0.x, q0.y, q0.y);
        a_dup[sr][SWZ(sa, 1)] = make_float4(q0.z, q0.z, q0.w, q0.w);
        a_dup[sr][SWZ(sa, 2)] = make_float4(q1.x, q1.x, q1.y, q1.y);
        a_dup[sr][SWZ(sa, 3)] = make_float4(q1.z, q1.z, q1.w, q1.w);
    }

    // ============ Phase 2a: blocks 0..31 fold 8 scratch tiles ============
    if (b < 32) {
        if (tid == 0) spin_ge(&g_sync[b], (e + 1) * 8);
        __syncthreads();
        const float4* src = (const float4*)g_scratch + (size_t)b * 8 * 512;
        float4* dst = (float4*)g_red + (size_t)b * 512;
        #pragma unroll
        for (int h = 0; h < 2; ++h) {
            int i4 = tid + h * 256;
            float4 s = __ldcg(src + i4);
            #pragma unroll
            for (int i = 1; i < 8; ++i) {
                float4 a = __ldcg(src + (size_t)i * 512 + i4);
                s.x += a.x; s.y += a.y; s.z += a.z; s.w += a.w;
            }
            dst[i4] = s;
        }
        __syncthreads();
        if (tid == 0) arrive(&g_sync[32 + (b >> 3)]);
    }

    // ============ Phase 2b: blocks 0..3 fold 8 red tiles =================
    if (b < 4) {
        if (tid == 0) spin_ge(&g_sync[32 + b], (e + 1) * 8);
        __syncthreads();
        const float4* src = (const float4*)g_red + (size_t)b * 8 * 512;
        float4* dst = (float4*)g_red2 + (size_t)b * 512;
        #pragma unroll
        for (int h = 0; h < 2; ++h) {
            int i4 = tid + h * 256;
            float4 s = __ldcg(src + i4);
            #pragma unroll
            for (int i = 1; i < 8; ++i) {
                float4 a = __ldcg(src + (size_t)i * 512 + i4);
                s.x += a.x; s.y += a.y; s.z += a.z; s.w += a.w;
            }
            dst[i4] = s;
        }
        __syncthreads();
        if (tid == 0) arrive(&g_sync[36]);
    }

    // ====== Phase 2c+3: block 0 — fold 4 -> G, register Cholesky -> L ====
    if (b == 0) {
        if (tid == 0) spin_ge(&g_sync[36], (e + 1) * 4);
        __syncthreads();
        const float4* src = (const float4*)g_red2;
        #pragma unroll
        for (int h = 0; h < 2; ++h) {
            int f4 = tid + h * 256;
            float4 s = __ldcg(src + f4);
            #pragma unroll
            for (int i = 1; i < 4; ++i) {
                float4 a = __ldcg(src + (size_t)i * 512 + f4);
                s.x += a.x; s.y += a.y; s.z += a.z; s.w += a.w;
            }
            int c = f4 * 2;
            As[(c >> 5) * 33 + (c & 31)]             = make_float2(s.x, s.y);
            As[((c + 1) >> 5) * 33 + ((c + 1) & 31)] = make_float2(s.z, s.w);
        }
        __syncthreads();

        // register (p,q)-parallel Cholesky: thread holds A[wid+8s][lane]
        float2 a4[4];
        #pragma unroll
        for (int s = 0; s < 4; ++s) a4[s] = As[(wid + 8 * s) * 33 + lane];

        for (int k = 0; k < R; ++k) {
            float2* cb = colbuf + (k & 1) * 32;
            if (lane == k) {
                #pragma unroll
                for (int s = 0; s < 4; ++s) cb[wid + 8 * s] = a4[s];
            }
            __syncthreads();
            float dkk = cb[k].x;
            float rd  = rsqrtf(dkk + EPSF);
            float2 cq = cb[lane];
            float2 lq = make_float2(cq.x * rd, cq.y * rd);
            #pragma unroll
            for (int s = 0; s < 4; ++s) {
                int p = wid + 8 * s;
                float2 cp = cb[p];
                float2 lp = make_float2(cp.x * rd, cp.y * rd);
                if (p > k && lane > k) {
                    a4[s].x -= lp.x * lq.x + lp.y * lq.y;
                    a4[s].y -= lp.y * lq.x - lp.x * lq.y;
                }
                if (lane == k) {
                    if (p == k)      a4[s] = make_float2((dkk + EPSF) * rd, 0.f);
                    else if (p > k)  a4[s] = lp;
                }
            }
        }
        #pragma unroll
        for (int s = 0; s < 4; ++s) g_L[(wid + 8 * s) * R + lane] = a4[s];
        __syncthreads();
        if (tid == 0) arrive(&g_sync[37]);
    }

    // ========= Phase 3b: blocks 0-3 backsub, one warp per column =========
    if (b < 4) {
        if (tid == 0) spin_ge(&g_sync[37], e + 1);
        __syncthreads();
        for (int el = tid; el < R * R; el += 256)
            As[(el >> 5) * 33 + (el & 31)] = __ldcg(&g_L[el]);
        __syncthreads();

        const int j = b * 8 + wid;
        const float invd = 1.0f / As[lane * 33 + lane].x;
        float2 accw = make_float2(0.f, 0.f);
        float2 wp   = make_float2(0.f, 0.f);
        for (int qq = j; qq >= 0; --qq) {
            float cre = (((lane == j) ? 1.f : 0.f) - accw.x) * invd;
            float cim = (-accw.y) * invd;
            float wr = __shfl_sync(0xffffffffu, cre, qq);
            float wi = __shfl_sync(0xffffffffu, cim, qq);
            if (lane == qq) { wp.x = wr; wp.y = wi; }
            float2 lqp = As[qq * 33 + lane];
            if (lane < qq) {
                accw.x += lqp.x * wr + lqp.y * wi;
                accw.y += lqp.x * wi - lqp.y * wr;
            }
        }
        g_W[lane * R + j] = wp;   // W[k][j]
        __syncthreads();
        if (tid == 0) arrive(&g_sync[38]);

        // deferred restage for blocks 0-3 (their smem was clobbered)
        __syncthreads();
        {
            const int sr = tid >> 3, sa = tid & 7;
            float4 p0 = *(const float4*)(xblk + sr * R + sa * 4);
            float4 p1 = *(const float4*)(xblk + sr * R + sa * 4 + 2);
            float4 q0 = *(const float4*)(xblk + (32 + sr) * R + sa * 4);
            float4 q1 = *(const float4*)(xblk + (32 + sr) * R + sa * 4 + 2);
            b_ns [sr][SWZ(sa, 0)] = make_float4(p0.x, p0.x, p0.y, p0.y);
            b_ns [sr][SWZ(sa, 1)] = make_float4(p0.z, p0.z, p0.w, p0.w);
            b_ns [sr][SWZ(sa, 2)] = make_float4(p1.x, p1.x, p1.y, p1.y);
            b_ns [sr][SWZ(sa, 3)] = make_float4(p1.z, p1.z, p1.w, p1.w);
            a_dup[sr][SWZ(sa, 0)] = make_float4(q0.x, q0.x, q0.y, q0.y);
            a_dup[sr][SWZ(sa, 1)] = make_float4(q0.z, q0.z, q0.w, q0.w);
            a_dup[sr][SWZ(sa, 2)] = make_float4(q1.x, q1.x, q1.y, q1.y);
            a_dup[sr][SWZ(sa, 3)] = make_float4(q1.z, q1.z, q1.w, q1.w);
        }
    }

    // ========== Phase 4: apply, broadcast-LDS + FFMA2 ====================
    if (tid == 0) spin_ge(&g_sync[38], (e + 1) * 4);
    __syncthreads();   // orders restage + W visibility for all warps
    {
        // lane j's W column, packed (wr,wi) — same 64 regs as wr[]+wi[]
        u64 wpk[R];
        #pragma unroll
        for (int k = 0; k < R; ++k) {
            float2 wv = __ldcg(&g_W[k * R + lane]);
            wpk[k] = pk2(wv.x, wv.y);
        }

        const float4 (*xt)[R] = (wid < 4)
            ? (const float4(*)[R])b_ns : (const float4(*)[R])a_dup;
        const int r0    = (wid & 3) * 8;
        const int mbase = (wid < 4) ? 0 : 32;
        float2* ob = out + (size_t)b * (ROWS_PER_BLK * R);

        #pragma unroll
        for (int r = 0; r < 8; r += 2) {
            const int m0 = r0 + r, m1 = m0 + 1;
            u64 aa0 = 0ull, ab0 = 0ull, aa1 = 0ull, ab1 = 0ull;
            #pragma unroll
            for (int k = 0; k < R; ++k) {
                const int sk = SWZ(k >> 2, k & 3);        // physical slot
                ulonglong2 v0 = *(const ulonglong2*)&xt[m0][sk]; // ((ar,ar),(ai,ai))
                ulonglong2 v1 = *(const ulonglong2*)&xt[m1][sk];
                aa0 = ffma2(v0.x, wpk[k], aa0);
                ab0 = ffma2(v0.y, wpk[k], ab0);
                aa1 = ffma2(v1.x, wpk[k], aa1);
                ab1 = ffma2(v1.y, wpk[k], ab1);
            }
            float2 A0 = upk2(aa0), B0 = upk2(ab0);
            float2 A1 = upk2(aa1), B1 = upk2(ab1);
            // re = sum ar*wr - ai*wi ; im = sum ar*wi + ai*wr
            ob[(mbase + m0) * R + lane] = make_float2(A0.x - B0.y, A0.y + B0.x);
            ob[(mbase + m1) * R + lane] = make_float2(A1.x - B1.y, A1.y + B1.x);
        }
    }
}

// ---------------------------------------------------------------------------
extern "C" void kernel_launch(void* const* d_in, const int* in_sizes, int n_in,
                              void* d_out, int out_size) {
    const float2* x  = (const float2*)d_in[0];
    float2* out      = (float2*)d_out;

    fused_kernel<<<NB, 256>>>(x, out);
}

// round 11
// speedup vs baseline: 1.4465x; 1.1128x over previous
#include <cuda_runtime.h>

#define EPSF 1e-10f

static const int R  = 32;
static const int NB = 256;          // co-resident blocks (<= 2/SM * 148)
static const int ROWS_PER_BLK = 64; // 2 tiles of 32

__device__ float2   g_scratch[NB * R * R];  // 2 MB partial Grams
__device__ float2   g_red[16 * R * R];      // 128 KB level-1 folds
__device__ float2   g_L[R * R];             // Cholesky factor
__device__ float2   g_W[R * R];             // L^{-H}
// sync counters (never reset): [0..15] gram groups (16 arr each),
// [16] fold1 done (16 arr), [17] chol done (1 arr), [18] W ready (4 arr)
__device__ unsigned g_sync[32];

typedef unsigned long long u64;

// ---- packed f32x2 helpers (FFMA2 only reachable via PTX) ----
__device__ __forceinline__ u64 pk2(float lo, float hi) {
    u64 r; asm("mov.b64 %0, {%1,%2};" : "=l"(r) : "f"(lo), "f"(hi)); return r;
}
__device__ __forceinline__ float2 upk2(u64 v) {
    float lo, hi; asm("mov.b64 {%0,%1}, %2;" : "=f"(lo), "=f"(hi) : "l"(v));
    return make_float2(lo, hi);
}
__device__ __forceinline__ u64 ffma2(u64 a, u64 b, u64 c) {
    u64 d; asm("fma.rn.f32x2 %0, %1, %2, %3;" : "=l"(d) : "l"(a), "l"(b), "l"(c)); return d;
}
__device__ __forceinline__ u64 fadd2(u64 a, u64 b) {
    u64 d; asm("add.rn.f32x2 %0, %1, %2;" : "=l"(d) : "l"(a), "l"(b)); return d;
}

// ---- flag primitives (tid-0 only; caller wraps with __syncthreads) ----
__device__ __forceinline__ unsigned arrive(unsigned* ctr) {
    __threadfence();                       // release
    return atomicAdd(ctr, 1u);
}
__device__ __forceinline__ void spin_ge(unsigned* ctr, unsigned target) {
    while ((int)(*((volatile unsigned*)ctr) - target) < 0) { }
    __threadfence();                       // acquire
}

// Bank-conflict-free smem column map: logical col c = 4a+d  ->  slot 8d+a.
#define SWZ(a, d) (8 * (d) + (a))

// ---------------------------------------------------------------------------
// Fused persistent kernel, producer-consumer synchronized:
//   gram(256) -> [restage overlap] fold1(16x16) -> fold2+chol(1)
//   -> backsub(4) -> apply(256, broadcast-LDS + FFMA2, W via smem)
// ---------------------------------------------------------------------------
__global__ void __launch_bounds__(256, 2)
fused_kernel(const float2* __restrict__ x, float2* __restrict__ out) {
    __shared__ __align__(16) char sraw[41 * 1024];
    float4 (*a_dup)[R] = reinterpret_cast<float4(*)[R]>(sraw);          // 16KB
    float4 (*b_ns)[R]  = reinterpret_cast<float4(*)[R]>(sraw + 16384);  // 16KB
    u64*    red        = reinterpret_cast<u64*>(sraw);                  // 24KB transient
    float2* As         = reinterpret_cast<float2*>(sraw);               // 8.4KB transient
    float2* colbuf     = reinterpret_cast<float2*>(sraw + 28 * 1024);   // [2][32]
    float2* wsm        = reinterpret_cast<float2*>(sraw + 32 * 1024);   // 8KB W copy

    const int tid  = threadIdx.x;
    const int b    = blockIdx.x;
    const int lane = tid & 31;
    const int wid  = tid >> 5;

    const float2* xblk = x + (size_t)b * (ROWS_PER_BLK * R);

    // ======================= Phase 1: partial Gram =======================
    {
        const int mg  = tid >> 6;
        const int t64 = tid & 63;
        const int ia  = t64 >> 3;          // A column group (i0 = 4*ia)
        const int ja  = t64 & 7;           // B column group (j0 = 4*ja)
        const int i0  = ia * 4;
        const int j0  = ja * 4;
        const int sr  = tid >> 3;          // staging row 0..31
        const int sa  = tid & 7;           // staging col group a

        u64 acc[4][4];
        #pragma unroll
        for (int a_ = 0; a_ < 4; ++a_)
            #pragma unroll
            for (int c_ = 0; c_ < 4; ++c_) acc[a_][c_] = 0ull;

        for (int t = 0; t < 2; ++t) {
            float4 p0 = *(const float4*)(xblk + (t * 32 + sr) * R + sa * 4);
            float4 p1 = *(const float4*)(xblk + (t * 32 + sr) * R + sa * 4 + 2);

            a_dup[sr][SWZ(sa, 0)] = make_float4(p0.x, p0.x, p0.y, p0.y);
            b_ns [sr][SWZ(sa, 0)] = make_float4(p0.x, p0.y, p0.y, -p0.x);
            a_dup[sr][SWZ(sa, 1)] = make_float4(p0.z, p0.z, p0.w, p0.w);
            b_ns [sr][SWZ(sa, 1)] = make_float4(p0.z, p0.w, p0.w, -p0.z);
            a_dup[sr][SWZ(sa, 2)] = make_float4(p1.x, p1.x, p1.y, p1.y);
            b_ns [sr][SWZ(sa, 2)] = make_float4(p1.x, p1.y, p1.y, -p1.x);
            a_dup[sr][SWZ(sa, 3)] = make_float4(p1.z, p1.z, p1.w, p1.w);
            b_ns [sr][SWZ(sa, 3)] = make_float4(p1.z, p1.w, p1.w, -p1.z);
            __syncthreads();

            #pragma unroll
            for (int mm = 0; mm < 8; ++mm) {
                const int m = mg + mm * 4;
                u64 A[4][2], B[4][2];
                #pragma unroll
                for (int d = 0; d < 4; ++d) {
                    float4 av = a_dup[m][SWZ(ia, d)];
                    A[d][0] = pk2(av.x, av.y); A[d][1] = pk2(av.z, av.w);
                    float4 bv = b_ns[m][SWZ(ja, d)];
                    B[d][0] = pk2(bv.x, bv.y); B[d][1] = pk2(bv.z, bv.w);
                }
                #pragma unroll
                for (int di = 0; di < 4; ++di)
                    #pragma unroll
                    for (int dj = 0; dj < 4; ++dj) {
                        acc[di][dj] = ffma2(A[di][0], B[dj][0], acc[di][dj]);
                        acc[di][dj] = ffma2(A[di][1], B[dj][1], acc[di][dj]);
                    }
            }
            __syncthreads();
        }

        if (mg > 0) {
            u64* dst = red + ((mg - 1) * 64 + t64) * 16;
            #pragma unroll
            for (int di = 0; di < 4; ++di)
                #pragma unroll
                for (int dj = 0; dj < 4; ++dj) dst[di * 4 + dj] = acc[di][dj];
        }
        __syncthreads();
        if (mg == 0) {
            #pragma unroll
            for (int g = 0; g < 3; ++g) {
                const u64* srcp = red + (g * 64 + t64) * 16;
                #pragma unroll
                for (int di = 0; di < 4; ++di)
                    #pragma unroll
                    for (int dj = 0; dj < 4; ++dj)
                        acc[di][dj] = fadd2(acc[di][dj], srcp[di * 4 + dj]);
            }
            float4* gout = reinterpret_cast<float4*>(g_scratch + b * (R * R));
            #pragma unroll
            for (int di = 0; di < 4; ++di) {
                float2 c0 = upk2(acc[di][0]), c1 = upk2(acc[di][1]);
                float2 c2 = upk2(acc[di][2]), c3 = upk2(acc[di][3]);
                int base = ((i0 + di) * R + j0) >> 1;
                gout[base]     = make_float4(c0.x, c0.y, c1.x, c1.y);
                gout[base + 1] = make_float4(c2.x, c2.y, c3.x, c3.y);
            }
        }
    }
    __syncthreads();

    // epoch ticket from own gram-group arrival (16 arrivals/group/replay)
    unsigned e = 0;
    if (tid == 0) e = arrive(&g_sync[b >> 4]) >> 4;

    // ===== Restage x into (r,r,i,i) SWZ layout for the LDS apply =========
    // rows 0..31 -> b_ns, rows 32..63 -> a_dup. Blocks >=4 do it here so it
    // overlaps the fold/chol/backsub chain; blocks 0-3 defer (their smem is
    // clobbered by As/colbuf during chol+backsub).
    if (b >= 4) {
        const int sr = tid >> 3, sa = tid & 7;
        float4 p0 = *(const float4*)(xblk + sr * R + sa * 4);
        float4 p1 = *(const float4*)(xblk + sr * R + sa * 4 + 2);
        float4 q0 = *(const float4*)(xblk + (32 + sr) * R + sa * 4);
        float4 q1 = *(const float4*)(xblk + (32 + sr) * R + sa * 4 + 2);
        b_ns [sr][SWZ(sa, 0)] = make_float4(p0.x, p0.x, p0.y, p0.y);
        b_ns [sr][SWZ(sa, 1)] = make_float4(p0.z, p0.z, p0.w, p0.w);
        b_ns [sr][SWZ(sa, 2)] = make_float4(p1.x, p1.x, p1.y, p1.y);
        b_ns [sr][SWZ(sa, 3)] = make_float4(p1.z, p1.z, p1.w, p1.w);
        a_dup[sr][SWZ(sa, 0)] = make_float4(q0.x, q0.x, q0.y, q0.y);
        a_dup[sr][SWZ(sa, 1)] = make_float4(q0.z, q0.z, q0.w, q0.w);
        a_dup[sr][SWZ(sa, 2)] = make_float4(q1.x, q1.x, q1.y, q1.y);
        a_dup[sr][SWZ(sa, 3)] = make_float4(q1.z, q1.z, q1.w, q1.w);
    }

    // ============ Phase 2a: blocks 0..15 fold 16 scratch tiles ===========
    if (b < 16) {
        if (tid == 0) spin_ge(&g_sync[b], (e + 1) * 16);
        __syncthreads();
        const float4* src = (const float4*)g_scratch + (size_t)b * 16 * 512;
        float4* dst = (float4*)g_red + (size_t)b * 512;
        #pragma unroll
        for (int h = 0; h < 2; ++h) {
            int i4 = tid + h * 256;
            float4 s = __ldcg(src + i4);
            #pragma unroll
            for (int i = 1; i < 16; ++i) {
                float4 a = __ldcg(src + (size_t)i * 512 + i4);
                s.x += a.x; s.y += a.y; s.z += a.z; s.w += a.w;
            }
            dst[i4] = s;
        }
        __syncthreads();
        if (tid == 0) arrive(&g_sync[16]);
    }

    // ====== Phase 2b+3: block 0 — fold 16 -> G, register Cholesky -> L ===
    if (b == 0) {
        if (tid == 0) spin_ge(&g_sync[16], (e + 1) * 16);
        __syncthreads();
        const float4* src = (const float4*)g_red;
        #pragma unroll
        for (int h = 0; h < 2; ++h) {
            int f4 = tid + h * 256;
            float4 s = __ldcg(src + f4);
            #pragma unroll
            for (int i = 1; i < 16; ++i) {
                float4 a = __ldcg(src + (size_t)i * 512 + f4);
                s.x += a.x; s.y += a.y; s.z += a.z; s.w += a.w;
            }
            int c = f4 * 2;
            As[(c >> 5) * 33 + (c & 31)]             = make_float2(s.x, s.y);
            As[((c + 1) >> 5) * 33 + ((c + 1) & 31)] = make_float2(s.z, s.w);
        }
        __syncthreads();

        // register (p,q)-parallel Cholesky: thread holds A[wid+8s][lane]
        float2 a4[4];
        #pragma unroll
        for (int s = 0; s < 4; ++s) a4[s] = As[(wid + 8 * s) * 33 + lane];

        for (int k = 0; k < R; ++k) {
            float2* cb = colbuf + (k & 1) * 32;
            if (lane == k) {
                #pragma unroll
                for (int s = 0; s < 4; ++s) cb[wid + 8 * s] = a4[s];
            }
            __syncthreads();
            float dkk = cb[k].x;
            float rd  = rsqrtf(dkk + EPSF);
            float2 cq = cb[lane];
            float2 lq = make_float2(cq.x * rd, cq.y * rd);
            #pragma unroll
            for (int s = 0; s < 4; ++s) {
                int p = wid + 8 * s;
                float2 cp = cb[p];
                float2 lp = make_float2(cp.x * rd, cp.y * rd);
                if (p > k && lane > k) {
                    a4[s].x -= lp.x * lq.x + lp.y * lq.y;
                    a4[s].y -= lp.y * lq.x - lp.x * lq.y;
                }
                if (lane == k) {
                    if (p == k)      a4[s] = make_float2((dkk + EPSF) * rd, 0.f);
                    else if (p > k)  a4[s] = lp;
                }
            }
        }
        #pragma unroll
        for (int s = 0; s < 4; ++s) g_L[(wid + 8 * s) * R + lane] = a4[s];
        __syncthreads();
        if (tid == 0) arrive(&g_sync[17]);
    }

    // ========= Phase 3b: blocks 0-3 backsub, one warp per column =========
    if (b < 4) {
        if (tid == 0) spin_ge(&g_sync[17], e + 1);
        __syncthreads();
        for (int el = tid; el < R * R; el += 256)
            As[(el >> 5) * 33 + (el & 31)] = __ldcg(&g_L[el]);
        __syncthreads();

        const int j = b * 8 + wid;
        const float invd = 1.0f / As[lane * 33 + lane].x;
        float2 accw = make_float2(0.f, 0.f);
        float2 wp   = make_float2(0.f, 0.f);
        for (int qq = j; qq >= 0; --qq) {
            float cre = (((lane == j) ? 1.f : 0.f) - accw.x) * invd;
            float cim = (-accw.y) * invd;
            float wr = __shfl_sync(0xffffffffu, cre, qq);
            float wi = __shfl_sync(0xffffffffu, cim, qq);
            if (lane == qq) { wp.x = wr; wp.y = wi; }
            float2 lqp = As[qq * 33 + lane];
            if (lane < qq) {
                accw.x += lqp.x * wr + lqp.y * wi;
                accw.y += lqp.x * wi - lqp.y * wr;
            }
        }
        g_W[lane * R + j] = wp;   // W[k][j]
        __syncthreads();
        if (tid == 0) arrive(&g_sync[18]);

        // deferred restage for blocks 0-3 (their smem was clobbered)
        __syncthreads();
        {
            const int sr = tid >> 3, sa = tid & 7;
            float4 p0 = *(const float4*)(xblk + sr * R + sa * 4);
            float4 p1 = *(const float4*)(xblk + sr * R + sa * 4 + 2);
            float4 q0 = *(const float4*)(xblk + (32 + sr) * R + sa * 4);
            float4 q1 = *(const float4*)(xblk + (32 + sr) * R + sa * 4 + 2);
            b_ns [sr][SWZ(sa, 0)] = make_float4(p0.x, p0.x, p0.y, p0.y);
            b_ns [sr][SWZ(sa, 1)] = make_float4(p0.z, p0.z, p0.w, p0.w);
            b_ns [sr][SWZ(sa, 2)] = make_float4(p1.x, p1.x, p1.y, p1.y);
            b_ns [sr][SWZ(sa, 3)] = make_float4(p1.z, p1.z, p1.w, p1.w);
            a_dup[sr][SWZ(sa, 0)] = make_float4(q0.x, q0.x, q0.y, q0.y);
            a_dup[sr][SWZ(sa, 1)] = make_float4(q0.z, q0.z, q0.w, q0.w);
            a_dup[sr][SWZ(sa, 2)] = make_float4(q1.x, q1.x, q1.y, q1.y);
            a_dup[sr][SWZ(sa, 3)] = make_float4(q1.z, q1.z, q1.w, q1.w);
        }
    }

    // ========== Phase 4: apply, broadcast-LDS + FFMA2, W via smem ========
    if (tid == 0) spin_ge(&g_sync[18], (e + 1) * 4);
    __syncthreads();   // orders restage + W visibility for all warps

    // stage W into smem once per block (8KB LDG instead of 8KB per warp)
    {
        float4* w4 = reinterpret_cast<float4*>(wsm);
        const float4* gw4 = reinterpret_cast<const float4*>(g_W);
        w4[tid]       = __ldcg(gw4 + tid);
        w4[tid + 256] = __ldcg(gw4 + tid + 256);
    }
    __syncthreads();
    {
        // lane j's W column, packed (wr,wi), from conflict-free LDS
        u64 wpk[R];
        #pragma unroll
        for (int k = 0; k < R; ++k) {
            float2 wv = wsm[k * R + lane];
            wpk[k] = pk2(wv.x, wv.y);
        }

        const float4 (*xt)[R] = (wid < 4)
            ? (const float4(*)[R])b_ns : (const float4(*)[R])a_dup;
        const int r0    = (wid & 3) * 8;
        const int mbase = (wid < 4) ? 0 : 32;
        float2* ob = out + (size_t)b * (ROWS_PER_BLK * R);

        #pragma unroll
        for (int r = 0; r < 8; r += 2) {
            const int m0 = r0 + r, m1 = m0 + 1;
            u64 aa0 = 0ull, ab0 = 0ull, aa1 = 0ull, ab1 = 0ull;
            #pragma unroll
            for (int k = 0; k < R; ++k) {
                const int sk = SWZ(k >> 2, k & 3);        // physical slot
                ulonglong2 v0 = *(const ulonglong2*)&xt[m0][sk]; // ((ar,ar),(ai,ai))
                ulonglong2 v1 = *(const ulonglong2*)&xt[m1][sk];
                aa0 = ffma2(v0.x, wpk[k], aa0);
                ab0 = ffma2(v0.y, wpk[k], ab0);
                aa1 = ffma2(v1.x, wpk[k], aa1);
                ab1 = ffma2(v1.y, wpk[k], ab1);
            }
            float2 A0 = upk2(aa0), B0 = upk2(ab0);
            float2 A1 = upk2(aa1), B1 = upk2(ab1);
            // re = sum ar*wr - ai*wi ; im = sum ar*wi + ai*wr
            ob[(mbase + m0) * R + lane] = make_float2(A0.x - B0.y, A0.y + B0.x);
            ob[(mbase + m1) * R + lane] = make_float2(A1.x - B1.y, A1.y + B1.x);
        }
    }
}

// ---------------------------------------------------------------------------
extern "C" void kernel_launch(void* const* d_in, const int* in_sizes, int n_in,
                              void* d_out, int out_size) {
    const float2* x  = (const float2*)d_in[0];
    float2* out      = (float2*)d_out;

    fused_kernel<<<NB, 256>>>(x, out);
}